// round 13
// baseline (speedup 1.0000x reference)
#include <cuda_runtime.h>
#include <cstdint>

#define Nn 50000
#define Mm 24
#define FN 92
#define FE 41
#define Ff 64
#define Cc 128

typedef unsigned long long ull;

// ---- scratch (static device globals; no allocation) ----
__device__ float g_bufA[Nn * Ff];             // 12.8 MB
__device__ float g_bufB[Nn * Ff];             // 12.8 MB
__device__ float g_S[(size_t)Nn * Cc];        // 25.6 MB (pair layout)
__device__ float g_P[(size_t)Nn * Cc];        // 25.6 MB (pair layout)
__device__ float g_ef2[(size_t)Nn * 1152];    // 230.4 MB fragment-ready padded ef
__device__ uint32_t g_Ua[3 * 8 * 6 * 4 * 32]; // pre-fragmented tf32 A operands
__device__ float g_dv[3 * Cc];                // folded edge bias

// ---- f32x2 packed helpers ----
__device__ __forceinline__ ull pack_dup(float x) {
    ull r; asm("mov.b64 %0, {%1, %1};" : "=l"(r) : "f"(x)); return r;
}
__device__ __forceinline__ ull pack2(float x, float y) {
    ull r; asm("mov.b64 %0, {%1, %2};" : "=l"(r) : "f"(x), "f"(y)); return r;
}
__device__ __forceinline__ void unpack2(ull v, float& x, float& y) {
    asm("mov.b64 {%0, %1}, %2;" : "=f"(x), "=f"(y) : "l"(v));
}
__device__ __forceinline__ void fma2(ull& acc, ull a, ull b) {
    asm("fma.rn.f32x2 %0, %1, %2, %0;" : "+l"(acc) : "l"(a), "l"(b));
}

// ---- fast activations (MUFU) ----
__device__ __forceinline__ float ex2_(float x) { float r; asm("ex2.approx.f32 %0, %1;" : "=f"(r) : "f"(x)); return r; }
__device__ __forceinline__ float lg2_(float x) { float r; asm("lg2.approx.f32 %0, %1;" : "=f"(r) : "f"(x)); return r; }
__device__ __forceinline__ float rcp_(float x) { float r; asm("rcp.approx.f32 %0, %1;" : "=f"(r) : "f"(x)); return r; }

__device__ __forceinline__ float sigmoidf_(float x) {
    return rcp_(1.0f + ex2_(-1.4426950408889634f * x));
}
__device__ __forceinline__ float softplusf_(float x) {
    float a = fabsf(x);
    float e = ex2_(-1.4426950408889634f * a);
    return fmaf(lg2_(1.0f + e), 0.6931471805599453f, fmaxf(x, 0.0f));
}

// ---- tf32 helpers ----
__device__ __forceinline__ uint32_t cvt_tf32(float x) {
    uint32_t r; asm("cvt.rna.tf32.f32 %0, %1;" : "=r"(r) : "f"(x)); return r;
}
__device__ __forceinline__ void mma_tf32(float* c,
                                         uint32_t a0, uint32_t a1, uint32_t a2, uint32_t a3,
                                         uint32_t b0, uint32_t b1) {
    asm volatile("mma.sync.aligned.m16n8k8.row.col.f32.tf32.tf32.f32 "
                 "{%0,%1,%2,%3}, {%4,%5,%6,%7}, {%8,%9}, {%0,%1,%2,%3};"
                 : "+f"(c[0]), "+f"(c[1]), "+f"(c[2]), "+f"(c[3])
                 : "r"(a0), "r"(a1), "r"(a2), "r"(a3), "r"(b0), "r"(b1));
}

// ---- cp.async helpers ----
__device__ __forceinline__ void cp16(uint32_t dst, const void* src) {
    asm volatile("cp.async.cg.shared.global [%0], [%1], 16;" :: "r"(dst), "l"(src));
}
__device__ __forceinline__ void cp_commit() { asm volatile("cp.async.commit_group;"); }
__device__ __forceinline__ void cp_wait1() { asm volatile("cp.async.wait_group 1;"); }
__device__ __forceinline__ void cp_wait0() { asm volatile("cp.async.wait_group 0;"); }

// ---- kernel 0: pre-transform ef into fragment-ready padded layout (verified R8) ----
// g_ef2[((n*9 + nt*3 + kt)*32 + li)*4 + j] = ef[n][nt*8 + li/4][16kt + li%4 + 4j] (0 if k>=41)
__global__ void __launch_bounds__(256) k_efpad(const float* __restrict__ ef) {
    __shared__ float s_raw[8 * 24 * FE];  // 31.5 KB
    int nbase = blockIdx.x * 8;
    const float* src = ef + (size_t)nbase * 24 * FE;
    for (int i = threadIdx.x; i < 8 * 24 * FE; i += 256)
        s_raw[i] = src[i];
    __syncthreads();
    float* dstb = g_ef2 + (size_t)nbase * 1152;
    for (int o = threadIdx.x; o < 8 * 1152; o += 256) {
        int nl = o / 1152, r = o - nl * 1152;
        int grp = r >> 7;               // nt*3 + kt  (0..8)
        int nt = grp / 3, kt = grp - nt * 3;
        int li = (r >> 2) & 31, j = r & 3;
        int m = nt * 8 + (li >> 2);
        int k = 16 * kt + (li & 3) + 4 * j;
        float v = (k < FE) ? s_raw[nl * 24 * FE + m * FE + k] : 0.0f;
        dstb[o] = v;
    }
}

// ---- kernel 1: node0 = node_fea @ Wn + bn ----
__global__ void __launch_bounds__(256) k_node_in(const float* __restrict__ nf,
                                                 const float* __restrict__ Wn,
                                                 const float* __restrict__ bn) {
    __shared__ float s_nf[8 * FN];
    int nbase = blockIdx.x * 8;
    for (int i = threadIdx.x; i < 8 * FN; i += 256)
        s_nf[i] = nf[(size_t)nbase * FN + i];
    __syncthreads();
    int g = threadIdx.x >> 5, c = threadIdx.x & 31;
    ull acc = pack2(bn[2 * c], bn[2 * c + 1]);
    const float* nr = &s_nf[g * FN];
#pragma unroll 4
    for (int k = 0; k < FN; k++) {
        ull w = *(const ull*)&Wn[k * Ff + 2 * c];
        fma2(acc, pack_dup(nr[k]), w);
    }
    *(ull*)&g_bufA[(size_t)(nbase + g) * Ff + 2 * c] = acc;
}

// ---- kernel 2: fold U into pre-arranged tf32 A fragments + dv ----
__global__ void __launch_bounds__(256) k_fold(const float* __restrict__ We,
                                              const float* __restrict__ be,
                                              const float* __restrict__ W1,
                                              const float* __restrict__ W2,
                                              const float* __restrict__ W3) {
    int l = blockIdx.x >> 3, gr = blockIdx.x & 7;
    const float* W = (l == 0) ? W1 : ((l == 1) ? W2 : W3);
    for (int i = threadIdx.x; i < 16 * 48; i += 256) {
        int r = i / 48, k = i - r * 48;
        int c = (r < 8) ? (gr * 8 + r) : (64 + gr * 8 + (r - 8));
        float u = 0.0f;
        if (k < FE) {
#pragma unroll 8
            for (int q = 0; q < Ff; q++)
                u = fmaf(We[k * Ff + q], W[(size_t)(128 + q) * Cc + c], u);
        }
        int kt = k >> 3, kin = k & 7;
        int q = ((r >= 8) ? 1 : 0) + ((kin >= 4) ? 2 : 0);
        int ln = (r & 7) * 4 + (kin & 3);
        g_Ua[(((l * 8 + gr) * 6 + kt) * 4 + q) * 32 + ln] = cvt_tf32(u);
    }
    if (threadIdx.x < 16) {
        int c = gr * 16 + threadIdx.x;
        float dv = 0.0f;
#pragma unroll 8
        for (int q = 0; q < Ff; q++)
            dv = fmaf(be[q], W[(size_t)(128 + q) * Cc + c], dv);
        g_dv[l * Cc + c] = dv;
    }
}

// ---- kernel 3: per-layer S/P precompute (R10: STG.128 stores, 32 nodes/block) ----
__global__ void __launch_bounds__(256) k_SP(int srcSel, const float* __restrict__ W,
                                            const float* __restrict__ b, int l) {
    const float* node = srcSel ? g_bufB : g_bufA;
    __shared__ float s_nT[64 * 36];
    int nbase = blockIdx.x * 32;
    for (int i = threadIdx.x; i < 2048; i += 256) {
        int k = i & 63, nl = i >> 6;
        int n = nbase + nl;
        s_nT[k * 36 + nl] = (n < Nn) ? node[(size_t)n * 64 + k] : 0.0f;
    }
    __syncthreads();
    int j = threadIdx.x & 31, g = threadIdx.x >> 5;
    float2 bF = *(const float2*)&b[2 * j];
    float2 bC = *(const float2*)&b[64 + 2 * j];
    float2 dF = *(const float2*)&g_dv[l * Cc + 2 * j];
    float2 dC = *(const float2*)&g_dv[l * Cc + 64 + 2 * j];
    ull sF0 = pack2(bF.x + dF.x, bF.y + dF.y), sF1 = sF0, sF2 = sF0, sF3 = sF0;
    ull sC0 = pack2(bC.x + dC.x, bC.y + dC.y), sC1 = sC0, sC2 = sC0, sC3 = sC0;
    ull pF0 = 0, pF1 = 0, pF2 = 0, pF3 = 0;
    ull pC0 = 0, pC1 = 0, pC2 = 0, pC3 = 0;
#pragma unroll 4
    for (int k = 0; k < 64; k++) {
        ull wSf = *(const ull*)&W[(size_t)k * Cc + 2 * j];
        ull wSc = *(const ull*)&W[(size_t)k * Cc + 64 + 2 * j];
        ull wPf = *(const ull*)&W[(size_t)(64 + k) * Cc + 2 * j];
        ull wPc = *(const ull*)&W[(size_t)(64 + k) * Cc + 64 + 2 * j];
        float4 nv = *(const float4*)&s_nT[k * 36 + g * 4];
        ull b0 = pack_dup(nv.x);
        fma2(sF0, b0, wSf); fma2(sC0, b0, wSc); fma2(pF0, b0, wPf); fma2(pC0, b0, wPc);
        ull b1 = pack_dup(nv.y);
        fma2(sF1, b1, wSf); fma2(sC1, b1, wSc); fma2(pF1, b1, wPf); fma2(pC1, b1, wPc);
        ull b2 = pack_dup(nv.z);
        fma2(sF2, b2, wSf); fma2(sC2, b2, wSc); fma2(pF2, b2, wPf); fma2(pC2, b2, wPc);
        ull b3 = pack_dup(nv.w);
        fma2(sF3, b3, wSf); fma2(sC3, b3, wSc); fma2(pF3, b3, wPf); fma2(pC3, b3, wPc);
    }
    int n0 = nbase + g * 4;
    ull sFa[4] = {sF0, sF1, sF2, sF3}, sCa[4] = {sC0, sC1, sC2, sC3};
    ull pFa[4] = {pF0, pF1, pF2, pF3}, pCa[4] = {pC0, pC1, pC2, pC3};
#pragma unroll
    for (int t = 0; t < 4; t++) {
        int n = n0 + t;
        if (n < Nn) {
            float fx, fy, cx, cy;
            unpack2(sFa[t], fx, fy); unpack2(sCa[t], cx, cy);
            *(float4*)&g_S[(size_t)n * Cc + 4 * j] = make_float4(fx, cx, fy, cy);
            unpack2(pFa[t], fx, fy); unpack2(pCa[t], cx, cy);
            *(float4*)&g_P[(size_t)n * Cc + 4 * j] = make_float4(fx, cx, fy, cy);
        }
    }
}

// ---- kernel 4: fused conv layer, 2-deep pipeline over fragment-ready g_ef2 ----
__global__ void __launch_bounds__(256, 4) k_conv(int srcSel, int dstSel,
                                                 const int* __restrict__ idx,
                                                 const float* __restrict__ alpha_p,
                                                 float* __restrict__ outp, int l) {
    const float* nodein = srcSel ? g_bufB : g_bufA;
    float* dst = (dstSel == 0) ? g_bufA : ((dstSel == 1) ? g_bufB : outp);

    __shared__ __align__(16) float s_ef[3][1152];   // 13.5 KB triple-buffered fragment tile
    __shared__ __align__(16) int s_idx[16 * 24];    // 1.5 KB

    const int tid = threadIdx.x;
    const int w = tid >> 5, lane = tid & 31;
    const int lr = lane >> 2, lc = lane & 3;
    const int nbase = blockIdx.x * 16;

    // A fragments (24 coalesced loads, once per block)
    uint32_t Af[6][4];
    const uint32_t* Ua = g_Ua + (size_t)(l * 8 + w) * 6 * 128;
#pragma unroll
    for (int kt = 0; kt < 6; kt++)
#pragma unroll
        for (int q = 0; q < 4; q++)
            Af[kt][q] = Ua[kt * 128 + q * 32 + lane];

    uint32_t eb[3];
    eb[0] = (uint32_t)__cvta_generic_to_shared(&s_ef[0][0]);
    eb[1] = (uint32_t)__cvta_generic_to_shared(&s_ef[1][0]);
    eb[2] = (uint32_t)__cvta_generic_to_shared(&s_ef[2][0]);
    const bool extra = (tid < 32);

    // prologue: idx staging + prefetch n0 (group 0); prefetch n1 (group 1)
    if (tid < 96)
        cp16((uint32_t)__cvta_generic_to_shared(s_idx) + tid * 16, idx + (size_t)nbase * 24 + tid * 4);
    {
        const float4* src = (const float4*)(g_ef2 + (size_t)nbase * 1152);
        cp16(eb[0] + tid * 16, src + tid);
        if (extra) cp16(eb[0] + 4096 + tid * 16, src + 256 + tid);
        cp_commit();
        src += 288;
        cp16(eb[1] + tid * 16, src + tid);
        if (extra) cp16(eb[1] + 4096 + tid * 16, src + 256 + tid);
        cp_commit();
    }

    const float alpha = __ldg(alpha_p);
    const int jo = w * 8 + lr;  // orig feature index owned at lc==0
    int bi = 0, pf = 2;

    for (int ni = 0; ni < 16; ni++) {
        const int n = nbase + ni;

        cp_wait1();          // group for node ni complete; ni+1 in flight
        __syncthreads();     // all warps done with node ni-1's buffer

        // ---- prefetch node ni+2 into the freed buffer ----
        if (ni < 14) {
            const float4* src = (const float4*)(g_ef2 + (size_t)(n + 2) * 1152);
            uint32_t db = eb[pf];
            cp16(db + tid * 16, src + tid);
            if (extra) cp16(db + 4096 + tid * 16, src + 256 + tid);
        }
        cp_commit();         // uniform group accounting

        // ---- early loads: idx (int2 LDS) -> P float2 gathers + S + node-in ----
        int2 ii0 = *(const int2*)&s_idx[ni * 24 + 0 * 8 + 2 * lc];
        int2 ii1 = *(const int2*)&s_idx[ni * 24 + 1 * 8 + 2 * lc];
        int2 ii2 = *(const int2*)&s_idx[ni * 24 + 2 * 8 + 2 * lc];
        int iia[6] = {ii0.x, ii0.y, ii1.x, ii1.y, ii2.x, ii2.y};
        float2 Pv[6];
#pragma unroll
        for (int t = 0; t < 6; t++) {
            int iv = (iia[t] < 0) ? 0 : iia[t];
            Pv[t] = *(const float2*)&g_P[(size_t)iv * Cc + 2 * jo];
        }
        float2 Sv = *(const float2*)&g_S[(size_t)n * Cc + 2 * jo];
        float nin = __ldg(&nodein[(size_t)n * Ff + jo]);

        // ---- mma: 3 chains; B via linear conflict-free LDS.128 ----
        const float4* se = (const float4*)&s_ef[bi][0] + lane;
        float c0[4] = {0, 0, 0, 0}, c1[4] = {0, 0, 0, 0}, c2[4] = {0, 0, 0, 0};
        {
            float4 q0 = se[0], q1 = se[32], q2 = se[64];
            mma_tf32(c0, Af[0][0], Af[0][1], Af[0][2], Af[0][3], __float_as_uint(q0.x), __float_as_uint(q0.y));
            mma_tf32(c0, Af[1][0], Af[1][1], Af[1][2], Af[1][3], __float_as_uint(q0.z), __float_as_uint(q0.w));
            mma_tf32(c0, Af[2][0], Af[2][1], Af[2][2], Af[2][3], __float_as_uint(q1.x), __float_as_uint(q1.y));
            mma_tf32(c0, Af[3][0], Af[3][1], Af[3][2], Af[3][3], __float_as_uint(q1.z), __float_as_uint(q1.w));
            mma_tf32(c0, Af[4][0], Af[4][1], Af[4][2], Af[4][3], __float_as_uint(q2.x), __float_as_uint(q2.y));
            mma_tf32(c0, Af[5][0], Af[5][1], Af[5][2], Af[5][3], __float_as_uint(q2.z), __float_as_uint(q2.w));
        }
        {
            float4 q0 = se[96], q1 = se[128], q2 = se[160];
            mma_tf32(c1, Af[0][0], Af[0][1], Af[0][2], Af[0][3], __float_as_uint(q0.x), __float_as_uint(q0.y));
            mma_tf32(c1, Af[1][0], Af[1][1], Af[1][2], Af[1][3], __float_as_uint(q0.z), __float_as_uint(q0.w));
            mma_tf32(c1, Af[2][0], Af[2][1], Af[2][2], Af[2][3], __float_as_uint(q1.x), __float_as_uint(q1.y));
            mma_tf32(c1, Af[3][0], Af[3][1], Af[3][2], Af[3][3], __float_as_uint(q1.z), __float_as_uint(q1.w));
            mma_tf32(c1, Af[4][0], Af[4][1], Af[4][2], Af[4][3], __float_as_uint(q2.x), __float_as_uint(q2.y));
            mma_tf32(c1, Af[5][0], Af[5][1], Af[5][2], Af[5][3], __float_as_uint(q2.z), __float_as_uint(q2.w));
        }
        {
            float4 q0 = se[192], q1 = se[224], q2 = se[256];
            mma_tf32(c2, Af[0][0], Af[0][1], Af[0][2], Af[0][3], __float_as_uint(q0.x), __float_as_uint(q0.y));
            mma_tf32(c2, Af[1][0], Af[1][1], Af[1][2], Af[1][3], __float_as_uint(q0.z), __float_as_uint(q0.w));
            mma_tf32(c2, Af[2][0], Af[2][1], Af[2][2], Af[2][3], __float_as_uint(q1.x), __float_as_uint(q1.y));
            mma_tf32(c2, Af[3][0], Af[3][1], Af[3][2], Af[3][3], __float_as_uint(q1.z), __float_as_uint(q1.w));
            mma_tf32(c2, Af[4][0], Af[4][1], Af[4][2], Af[4][3], __float_as_uint(q2.x), __float_as_uint(q2.y));
            mma_tf32(c2, Af[5][0], Af[5][1], Af[5][2], Af[5][3], __float_as_uint(q2.z), __float_as_uint(q2.w));
        }

        // ---- epilogue: lane-local (filter, core) pairs ----
        float acc = 0.0f;
        if (iia[0] >= 0) acc += sigmoidf_(c0[0] + Sv.x + Pv[0].x) * softplusf_(c0[2] + Sv.y + Pv[0].y);
        if (iia[1] >= 0) acc += sigmoidf_(c0[1] + Sv.x + Pv[1].x) * softplusf_(c0[3] + Sv.y + Pv[1].y);
        if (iia[2] >= 0) acc += sigmoidf_(c1[0] + Sv.x + Pv[2].x) * softplusf_(c1[2] + Sv.y + Pv[2].y);
        if (iia[3] >= 0) acc += sigmoidf_(c1[1] + Sv.x + Pv[3].x) * softplusf_(c1[3] + Sv.y + Pv[3].y);
        if (iia[4] >= 0) acc += sigmoidf_(c2[0] + Sv.x + Pv[4].x) * softplusf_(c2[2] + Sv.y + Pv[4].y);
        if (iia[5] >= 0) acc += sigmoidf_(c2[1] + Sv.x + Pv[5].x) * softplusf_(c2[3] + Sv.y + Pv[5].y);

        acc += __shfl_xor_sync(0xffffffffu, acc, 1);
        acc += __shfl_xor_sync(0xffffffffu, acc, 2);

        if (lc == 0)
            dst[(size_t)n * Ff + jo] = softplusf_(fmaf(alpha, nin, acc));

        bi = (bi == 2) ? 0 : bi + 1;
        pf = (pf == 2) ? 0 : pf + 1;
    }
}

extern "C" void kernel_launch(void* const* d_in, const int* in_sizes, int n_in,
                              void* d_out, int out_size) {
    const float* nf  = (const float*)d_in[0];
    const float* ef  = (const float*)d_in[1];
    const int*   idx = (const int*)d_in[2];
    const float* Wn  = (const float*)d_in[3];
    const float* bn  = (const float*)d_in[4];
    const float* We  = (const float*)d_in[5];
    const float* be  = (const float*)d_in[6];
    const float* W[3] = {(const float*)d_in[7], (const float*)d_in[10], (const float*)d_in[13]};
    const float* b[3] = {(const float*)d_in[8], (const float*)d_in[11], (const float*)d_in[14]};
    const float* a[3] = {(const float*)d_in[9], (const float*)d_in[12], (const float*)d_in[15]};
    float* out = (float*)d_out;

    k_efpad<<<Nn / 8, 256>>>(ef);                        // -> g_ef2 (one-time)
    k_node_in<<<Nn / 8, 256>>>(nf, Wn, bn);              // -> g_bufA
    k_fold<<<24, 256>>>(We, be, W[0], W[1], W[2]);       // -> g_Ua, g_dv

    const int spGrid = (Nn + 31) / 32;                   // 1563
    // layer 1: A -> B
    k_SP<<<spGrid, 256>>>(0, W[0], b[0], 0);
    k_conv<<<Nn / 16, 256>>>(0, 1, idx, a[0], out, 0);
    // layer 2: B -> A
    k_SP<<<spGrid, 256>>>(1, W[1], b[1], 1);
    k_conv<<<Nn / 16, 256>>>(1, 0, idx, a[1], out, 1);
    // layer 3: A -> d_out
    k_SP<<<spGrid, 256>>>(0, W[2], b[2], 2);
    k_conv<<<Nn / 16, 256>>>(0, 2, idx, a[2], out, 2);
}

// round 14
// speedup vs baseline: 1.3632x; 1.3632x over previous
#include <cuda_runtime.h>
#include <cstdint>

#define Nn 50000
#define Mm 24
#define FN 92
#define FE 41
#define Ff 64
#define Cc 128

typedef unsigned long long ull;

// ---- scratch (static device globals; no allocation) ----
__device__ float g_bufA[Nn * Ff];             // 12.8 MB
__device__ float g_bufB[Nn * Ff];             // 12.8 MB
__device__ float g_S[(size_t)Nn * Cc];        // 25.6 MB (pair layout: [2j]=filter_j, [2j+1]=core_j)
__device__ float g_P[(size_t)Nn * Cc];        // 25.6 MB (pair layout)
__device__ uint32_t g_Ua[3 * 8 * 6 * 4 * 32]; // pre-fragmented tf32 A operands
__device__ float g_dv[3 * Cc];                // folded edge bias (orig col layout)

// ---- f32x2 packed helpers ----
__device__ __forceinline__ ull pack_dup(float x) {
    ull r; asm("mov.b64 %0, {%1, %1};" : "=l"(r) : "f"(x)); return r;
}
__device__ __forceinline__ ull pack2(float x, float y) {
    ull r; asm("mov.b64 %0, {%1, %2};" : "=l"(r) : "f"(x), "f"(y)); return r;
}
__device__ __forceinline__ void unpack2(ull v, float& x, float& y) {
    asm("mov.b64 {%0, %1}, %2;" : "=f"(x), "=f"(y) : "l"(v));
}
__device__ __forceinline__ void fma2(ull& acc, ull a, ull b) {
    asm("fma.rn.f32x2 %0, %1, %2, %0;" : "+l"(acc) : "l"(a), "l"(b));
}

// ---- fast activations (MUFU) ----
__device__ __forceinline__ float ex2_(float x) { float r; asm("ex2.approx.f32 %0, %1;" : "=f"(r) : "f"(x)); return r; }
__device__ __forceinline__ float lg2_(float x) { float r; asm("lg2.approx.f32 %0, %1;" : "=f"(r) : "f"(x)); return r; }
__device__ __forceinline__ float rcp_(float x) { float r; asm("rcp.approx.f32 %0, %1;" : "=f"(r) : "f"(x)); return r; }

__device__ __forceinline__ float sigmoidf_(float x) {
    return rcp_(1.0f + ex2_(-1.4426950408889634f * x));
}
__device__ __forceinline__ float softplusf_(float x) {
    float a = fabsf(x);
    float e = ex2_(-1.4426950408889634f * a);
    return fmaf(lg2_(1.0f + e), 0.6931471805599453f, fmaxf(x, 0.0f));
}

// ---- tf32 helpers ----
__device__ __forceinline__ uint32_t cvt_tf32(float x) {
    uint32_t r; asm("cvt.rna.tf32.f32 %0, %1;" : "=r"(r) : "f"(x)); return r;
}
__device__ __forceinline__ void mma_tf32(float* c,
                                         uint32_t a0, uint32_t a1, uint32_t a2, uint32_t a3,
                                         uint32_t b0, uint32_t b1) {
    asm volatile("mma.sync.aligned.m16n8k8.row.col.f32.tf32.tf32.f32 "
                 "{%0,%1,%2,%3}, {%4,%5,%6,%7}, {%8,%9}, {%0,%1,%2,%3};"
                 : "+f"(c[0]), "+f"(c[1]), "+f"(c[2]), "+f"(c[3])
                 : "r"(a0), "r"(a1), "r"(a2), "r"(a3), "r"(b0), "r"(b1));
}

// ---- cp.async helpers ----
__device__ __forceinline__ void cp4(uint32_t dst, const void* src) {
    asm volatile("cp.async.ca.shared.global [%0], [%1], 4;" :: "r"(dst), "l"(src));
}
__device__ __forceinline__ void cp16(uint32_t dst, const void* src) {
    asm volatile("cp.async.cg.shared.global [%0], [%1], 16;" :: "r"(dst), "l"(src));
}
__device__ __forceinline__ void cp_commit() {
    asm volatile("cp.async.commit_group;");
}
__device__ __forceinline__ void cp_wait1() {
    asm volatile("cp.async.wait_group 1;");
}

// ef smem k-map within a row (stride 48): quads (k, k+4, k+8, k+12) contiguous
__device__ __host__ __forceinline__ int ef_off(int k) {
    return ((k >> 4) << 4) + ((k & 3) << 2) + (((k >> 3) & 1) << 1) + ((k >> 2) & 1);
}

// ---- kernel 1: node0 = node_fea @ Wn + bn ----
__global__ void __launch_bounds__(256) k_node_in(const float* __restrict__ nf,
                                                 const float* __restrict__ Wn,
                                                 const float* __restrict__ bn) {
    __shared__ float s_nf[8 * FN];
    int nbase = blockIdx.x * 8;
    for (int i = threadIdx.x; i < 8 * FN; i += 256)
        s_nf[i] = nf[(size_t)nbase * FN + i];
    __syncthreads();
    int g = threadIdx.x >> 5, c = threadIdx.x & 31;
    ull acc = pack2(bn[2 * c], bn[2 * c + 1]);
    const float* nr = &s_nf[g * FN];
#pragma unroll 4
    for (int k = 0; k < FN; k++) {
        ull w = *(const ull*)&Wn[k * Ff + 2 * c];
        fma2(acc, pack_dup(nr[k]), w);
    }
    *(ull*)&g_bufA[(size_t)(nbase + g) * Ff + 2 * c] = acc;
}

// ---- kernel 2: fold U into pre-arranged tf32 A fragments + dv ----
__global__ void __launch_bounds__(256) k_fold(const float* __restrict__ We,
                                              const float* __restrict__ be,
                                              const float* __restrict__ W1,
                                              const float* __restrict__ W2,
                                              const float* __restrict__ W3) {
    int l = blockIdx.x >> 3, gr = blockIdx.x & 7;
    const float* W = (l == 0) ? W1 : ((l == 1) ? W2 : W3);
    for (int i = threadIdx.x; i < 16 * 48; i += 256) {
        int r = i / 48, k = i - r * 48;
        int c = (r < 8) ? (gr * 8 + r) : (64 + gr * 8 + (r - 8));
        float u = 0.0f;
        if (k < FE) {
#pragma unroll 8
            for (int q = 0; q < Ff; q++)
                u = fmaf(We[k * Ff + q], W[(size_t)(128 + q) * Cc + c], u);
        }
        int kt = k >> 3, kin = k & 7;
        int q = ((r >= 8) ? 1 : 0) + ((kin >= 4) ? 2 : 0);
        int ln = (r & 7) * 4 + (kin & 3);
        g_Ua[(((l * 8 + gr) * 6 + kt) * 4 + q) * 32 + ln] = cvt_tf32(u);
    }
    if (threadIdx.x < 16) {
        int c = gr * 16 + threadIdx.x;
        float dv = 0.0f;
#pragma unroll 8
        for (int q = 0; q < Ff; q++)
            dv = fmaf(be[q], W[(size_t)(128 + q) * Cc + c], dv);
        g_dv[l * Cc + c] = dv;
    }
}

// ---- kernel 3: per-layer S/P precompute (R7-exact: proven 918-µs config) ----
__global__ void __launch_bounds__(256) k_SP(int srcSel, const float* __restrict__ W,
                                            const float* __restrict__ b, int l) {
    const float* node = srcSel ? g_bufB : g_bufA;
    __shared__ float s_nT[64 * 16];
    int nbase = blockIdx.x * 16;
    for (int i = threadIdx.x; i < 1024; i += 256) {
        int k = i & 63, nl = i >> 6;
        s_nT[k * 16 + nl] = node[(size_t)(nbase + nl) * 64 + k];
    }
    __syncthreads();
    int c = threadIdx.x & 63, gq = threadIdx.x >> 6;
    float2 bv = ((const float2*)b)[c];
    float2 dv = ((const float2*)(g_dv + l * Cc))[c];
    ull s0 = pack2(bv.x + dv.x, bv.y + dv.y);
    ull s1 = s0, s2 = s0, s3 = s0;
    ull p0 = 0, p1 = 0, p2 = 0, p3 = 0;
#pragma unroll 4
    for (int k = 0; k < 64; k++) {
        ull wS = *(const ull*)&W[(size_t)k * Cc + 2 * c];
        ull wP = *(const ull*)&W[(size_t)(64 + k) * Cc + 2 * c];
        float4 nv = *(const float4*)&s_nT[k * 16 + gq * 4];
        ull b0 = pack_dup(nv.x); fma2(s0, b0, wS); fma2(p0, b0, wP);
        ull b1 = pack_dup(nv.y); fma2(s1, b1, wS); fma2(p1, b1, wP);
        ull b2 = pack_dup(nv.z); fma2(s2, b2, wS); fma2(p2, b2, wP);
        ull b3 = pack_dup(nv.w); fma2(s3, b3, wS); fma2(p3, b3, wP);
    }
    int n0 = nbase + gq * 4;
    int base = (c < 32) ? (4 * c) : (4 * c - 127);
    float x, y;
    unpack2(s0, x, y); g_S[(size_t)(n0 + 0) * Cc + base] = x; g_S[(size_t)(n0 + 0) * Cc + base + 2] = y;
    unpack2(s1, x, y); g_S[(size_t)(n0 + 1) * Cc + base] = x; g_S[(size_t)(n0 + 1) * Cc + base + 2] = y;
    unpack2(s2, x, y); g_S[(size_t)(n0 + 2) * Cc + base] = x; g_S[(size_t)(n0 + 2) * Cc + base + 2] = y;
    unpack2(s3, x, y); g_S[(size_t)(n0 + 3) * Cc + base] = x; g_S[(size_t)(n0 + 3) * Cc + base + 2] = y;
    unpack2(p0, x, y); g_P[(size_t)(n0 + 0) * Cc + base] = x; g_P[(size_t)(n0 + 0) * Cc + base + 2] = y;
    unpack2(p1, x, y); g_P[(size_t)(n0 + 1) * Cc + base] = x; g_P[(size_t)(n0 + 1) * Cc + base + 2] = y;
    unpack2(p2, x, y); g_P[(size_t)(n0 + 2) * Cc + base] = x; g_P[(size_t)(n0 + 2) * Cc + base + 2] = y;
    unpack2(p3, x, y); g_P[(size_t)(n0 + 3) * Cc + base] = x; g_P[(size_t)(n0 + 3) * Cc + base + 2] = y;
}

// ---- kernel 4: fused conv layer — R7 pipeline at PAIR granularity (8 syncs) ----
__global__ void __launch_bounds__(256, 4) k_conv(int srcSel, int dstSel,
                                                 const float* __restrict__ ef,
                                                 const int* __restrict__ idx,
                                                 const float* __restrict__ alpha_p,
                                                 float* __restrict__ outp, int l) {
    const float* nodein = srcSel ? g_bufB : g_bufA;
    float* dst = (dstSel == 0) ? g_bufA : ((dstSel == 1) ? g_bufB : outp);

    __shared__ __align__(16) float s_ef[6][24 * 48];   // 27 KB, 3 pair-slots x 2 nodes
    __shared__ __align__(16) int s_idx[16 * 24];       // 1.5 KB

    const int tid = threadIdx.x;
    const int w = tid >> 5, lane = tid & 31;
    const int lr = lane >> 2, lc = lane & 3;
    const int nbase = blockIdx.x * 16;

    // A fragments (24 coalesced loads, once per block)
    uint32_t Af[6][4];
    const uint32_t* Ua = g_Ua + (size_t)(l * 8 + w) * 6 * 128;
#pragma unroll
    for (int kt = 0; kt < 6; kt++)
#pragma unroll
        for (int q = 0; q < 4; q++)
            Af[kt][q] = Ua[kt * 128 + q * 32 + lane];

    // static zero pads: image of k=41..47 in every row, all 6 buffers
    for (int i = tid; i < 6 * 24 * 7; i += 256) {
        int bq = i / 168, r = i - bq * 168;
        int m = r / 7, k = 41 + (r - m * 7);
        s_ef[bq][m * 48 + ef_off(k)] = 0.0f;
    }

    // per-thread ef-prefetch dest offsets (node-invariant map)
    uint32_t eb[6];
#pragma unroll
    for (int q = 0; q < 6; q++)
        eb[q] = (uint32_t)__cvta_generic_to_shared(&s_ef[q][0]);
    uint32_t dq[4];
#pragma unroll
    for (int r = 0; r < 4; r++) {
        int t = tid + r * 256;
        int m = t / FE, k = t - m * FE;
        dq[r] = (uint32_t)(m * 48 + ef_off(k)) * 4;
    }
    const bool has3 = (tid < 24 * FE - 768);

    // prologue: idx staging + prefetch pair0 (nodes 0,1); pair1 (nodes 2,3)
    if (tid < 96)
        cp16((uint32_t)__cvta_generic_to_shared(s_idx) + tid * 16, idx + (size_t)nbase * 24 + tid * 4);
    {
        const float* src = ef + (size_t)nbase * 24 * FE;
#pragma unroll
        for (int q = 0; q < 2; q++) {
            cp4(eb[q] + dq[0], src + tid);
            cp4(eb[q] + dq[1], src + tid + 256);
            cp4(eb[q] + dq[2], src + tid + 512);
            if (has3) cp4(eb[q] + dq[3], src + tid + 768);
            src += 24 * FE;
        }
        cp_commit();
#pragma unroll
        for (int q = 2; q < 4; q++) {
            cp4(eb[q] + dq[0], src + tid);
            cp4(eb[q] + dq[1], src + tid + 256);
            cp4(eb[q] + dq[2], src + tid + 512);
            if (has3) cp4(eb[q] + dq[3], src + tid + 768);
            src += 24 * FE;
        }
        cp_commit();
    }

    const float alpha = __ldg(alpha_p);
    const int jo = w * 8 + lr;  // orig feature index owned at lc==0

    for (int p = 0; p < 8; p++) {   // pairs of nodes
        cp_wait1();          // pair p landed; pair p+1 may be in flight
        __syncthreads();     // all warps done with pair p-1's buffers

        // ---- prefetch pair p+2 into pair p-1's slot ----
        if (p < 6) {
            int slot = (p + 2) % 3;
            const float* src = ef + (size_t)(nbase + 2 * (p + 2)) * 24 * FE;
#pragma unroll
            for (int q = 0; q < 2; q++) {
                uint32_t db = eb[2 * slot + q];
                cp4(db + dq[0], src + tid);
                cp4(db + dq[1], src + tid + 256);
                cp4(db + dq[2], src + tid + 512);
                if (has3) cp4(db + dq[3], src + tid + 768);
                src += 24 * FE;
            }
        }
        cp_commit();         // uniform group accounting

        // ---- process the two nodes of this pair (no barrier between them) ----
#pragma unroll
        for (int half = 0; half < 2; half++) {
            const int ni = 2 * p + half;
            const int n = nbase + ni;
            const int bi = 2 * (p % 3) + half;

            // early loads: idx (int2 LDS) -> P float2 gathers + S + node-in
            int2 ii0 = *(const int2*)&s_idx[ni * 24 + 0 * 8 + 2 * lc];
            int2 ii1 = *(const int2*)&s_idx[ni * 24 + 1 * 8 + 2 * lc];
            int2 ii2 = *(const int2*)&s_idx[ni * 24 + 2 * 8 + 2 * lc];
            int iia[6] = {ii0.x, ii0.y, ii1.x, ii1.y, ii2.x, ii2.y};
            float2 Pv[6];
#pragma unroll
            for (int t = 0; t < 6; t++) {
                int iv = (iia[t] < 0) ? 0 : iia[t];
                Pv[t] = *(const float2*)&g_P[(size_t)iv * Cc + 2 * jo];
            }
            float2 Sv = *(const float2*)&g_S[(size_t)n * Cc + 2 * jo];
            float nin = __ldg(&nodein[(size_t)n * Ff + jo]);

            // mma: 3 chains; B operands via LDS.128 (two k-steps per load)
            const float* se = s_ef[bi];
            const float* r0 = se + (0 * 8 + lr) * 48 + lc * 4;
            const float* r1 = se + (1 * 8 + lr) * 48 + lc * 4;
            const float* r2 = se + (2 * 8 + lr) * 48 + lc * 4;
            float c0[4] = {0, 0, 0, 0}, c1[4] = {0, 0, 0, 0}, c2[4] = {0, 0, 0, 0};
#pragma unroll
            for (int t = 0; t < 3; t++) {
                float4 q0 = *(const float4*)(r0 + t * 16);
                float4 q1 = *(const float4*)(r1 + t * 16);
                float4 q2 = *(const float4*)(r2 + t * 16);
                mma_tf32(c0, Af[2 * t][0], Af[2 * t][1], Af[2 * t][2], Af[2 * t][3],
                         __float_as_uint(q0.x), __float_as_uint(q0.y));
                mma_tf32(c1, Af[2 * t][0], Af[2 * t][1], Af[2 * t][2], Af[2 * t][3],
                         __float_as_uint(q1.x), __float_as_uint(q1.y));
                mma_tf32(c2, Af[2 * t][0], Af[2 * t][1], Af[2 * t][2], Af[2 * t][3],
                         __float_as_uint(q2.x), __float_as_uint(q2.y));
                mma_tf32(c0, Af[2 * t + 1][0], Af[2 * t + 1][1], Af[2 * t + 1][2], Af[2 * t + 1][3],
                         __float_as_uint(q0.z), __float_as_uint(q0.w));
                mma_tf32(c1, Af[2 * t + 1][0], Af[2 * t + 1][1], Af[2 * t + 1][2], Af[2 * t + 1][3],
                         __float_as_uint(q1.z), __float_as_uint(q1.w));
                mma_tf32(c2, Af[2 * t + 1][0], Af[2 * t + 1][1], Af[2 * t + 1][2], Af[2 * t + 1][3],
                         __float_as_uint(q2.z), __float_as_uint(q2.w));
            }

            // epilogue: lane-local (filter, core) pairs
            float acc = 0.0f;
            if (iia[0] >= 0) acc += sigmoidf_(c0[0] + Sv.x + Pv[0].x) * softplusf_(c0[2] + Sv.y + Pv[0].y);
            if (iia[1] >= 0) acc += sigmoidf_(c0[1] + Sv.x + Pv[1].x) * softplusf_(c0[3] + Sv.y + Pv[1].y);
            if (iia[2] >= 0) acc += sigmoidf_(c1[0] + Sv.x + Pv[2].x) * softplusf_(c1[2] + Sv.y + Pv[2].y);
            if (iia[3] >= 0) acc += sigmoidf_(c1[1] + Sv.x + Pv[3].x) * softplusf_(c1[3] + Sv.y + Pv[3].y);
            if (iia[4] >= 0) acc += sigmoidf_(c2[0] + Sv.x + Pv[4].x) * softplusf_(c2[2] + Sv.y + Pv[4].y);
            if (iia[5] >= 0) acc += sigmoidf_(c2[1] + Sv.x + Pv[5].x) * softplusf_(c2[3] + Sv.y + Pv[5].y);

            acc += __shfl_xor_sync(0xffffffffu, acc, 1);
            acc += __shfl_xor_sync(0xffffffffu, acc, 2);

            if (lc == 0)
                dst[(size_t)n * Ff + jo] = softplusf_(fmaf(alpha, nin, acc));
        }
    }
}

extern "C" void kernel_launch(void* const* d_in, const int* in_sizes, int n_in,
                              void* d_out, int out_size) {
    const float* nf  = (const float*)d_in[0];
    const float* ef  = (const float*)d_in[1];
    const int*   idx = (const int*)d_in[2];
    const float* Wn  = (const float*)d_in[3];
    const float* bn  = (const float*)d_in[4];
    const float* We  = (const float*)d_in[5];
    const float* be  = (const float*)d_in[6];
    const float* W[3] = {(const float*)d_in[7], (const float*)d_in[10], (const float*)d_in[13]};
    const float* b[3] = {(const float*)d_in[8], (const float*)d_in[11], (const float*)d_in[14]};
    const float* a[3] = {(const float*)d_in[9], (const float*)d_in[12], (const float*)d_in[15]};
    float* out = (float*)d_out;

    k_node_in<<<Nn / 8, 256>>>(nf, Wn, bn);              // -> g_bufA
    k_fold<<<24, 256>>>(We, be, W[0], W[1], W[2]);       // -> g_Ua, g_dv

    // layer 1: A -> B
    k_SP<<<Nn / 16, 256>>>(0, W[0], b[0], 0);
    k_conv<<<Nn / 16, 256>>>(0, 1, ef, idx, a[0], out, 0);
    // layer 2: B -> A
    k_SP<<<Nn / 16, 256>>>(1, W[1], b[1], 1);
    k_conv<<<Nn / 16, 256>>>(1, 0, ef, idx, a[1], out, 1);
    // layer 3: A -> d_out
    k_SP<<<Nn / 16, 256>>>(0, W[2], b[2], 2);
    k_conv<<<Nn / 16, 256>>>(0, 2, ef, idx, a[2], out, 2);
}

// round 15
// speedup vs baseline: 1.5894x; 1.1660x over previous
#include <cuda_runtime.h>
#include <cstdint>

#define Nn 50000
#define Mm 24
#define FN 92
#define FE 41
#define Ff 64
#define Cc 128

typedef unsigned long long ull;

// ---- scratch (static device globals; no allocation) ----
__device__ float g_bufA[Nn * Ff];             // 12.8 MB
__device__ float g_bufB[Nn * Ff];             // 12.8 MB
__device__ float g_S[(size_t)Nn * Cc];        // 25.6 MB (pair layout: [2j]=filter_j, [2j+1]=core_j)
__device__ float g_P[(size_t)Nn * Cc];        // 25.6 MB (pair layout)
__device__ uint32_t g_Ua[3 * 8 * 6 * 4 * 32]; // pre-fragmented tf32 A operands
__device__ float g_dv[3 * Cc];                // folded edge bias (orig col layout)

// ---- f32x2 packed helpers ----
__device__ __forceinline__ ull pack_dup(float x) {
    ull r; asm("mov.b64 %0, {%1, %1};" : "=l"(r) : "f"(x)); return r;
}
__device__ __forceinline__ ull pack2(float x, float y) {
    ull r; asm("mov.b64 %0, {%1, %2};" : "=l"(r) : "f"(x), "f"(y)); return r;
}
__device__ __forceinline__ void unpack2(ull v, float& x, float& y) {
    asm("mov.b64 {%0, %1}, %2;" : "=f"(x), "=f"(y) : "l"(v));
}
__device__ __forceinline__ void fma2(ull& acc, ull a, ull b) {
    asm("fma.rn.f32x2 %0, %1, %2, %0;" : "+l"(acc) : "l"(a), "l"(b));
}

// ---- fast activations (MUFU) ----
__device__ __forceinline__ float ex2_(float x) { float r; asm("ex2.approx.f32 %0, %1;" : "=f"(r) : "f"(x)); return r; }
__device__ __forceinline__ float lg2_(float x) { float r; asm("lg2.approx.f32 %0, %1;" : "=f"(r) : "f"(x)); return r; }
__device__ __forceinline__ float rcp_(float x) { float r; asm("rcp.approx.f32 %0, %1;" : "=f"(r) : "f"(x)); return r; }

__device__ __forceinline__ float sigmoidf_(float x) {
    return rcp_(1.0f + ex2_(-1.4426950408889634f * x));
}
__device__ __forceinline__ float softplusf_(float x) {
    float a = fabsf(x);
    float e = ex2_(-1.4426950408889634f * a);
    return fmaf(lg2_(1.0f + e), 0.6931471805599453f, fmaxf(x, 0.0f));
}

// ---- tf32 helpers ----
__device__ __forceinline__ uint32_t cvt_tf32(float x) {
    uint32_t r; asm("cvt.rna.tf32.f32 %0, %1;" : "=r"(r) : "f"(x)); return r;
}
__device__ __forceinline__ void mma_tf32(float* c,
                                         uint32_t a0, uint32_t a1, uint32_t a2, uint32_t a3,
                                         uint32_t b0, uint32_t b1) {
    asm volatile("mma.sync.aligned.m16n8k8.row.col.f32.tf32.tf32.f32 "
                 "{%0,%1,%2,%3}, {%4,%5,%6,%7}, {%8,%9}, {%0,%1,%2,%3};"
                 : "+f"(c[0]), "+f"(c[1]), "+f"(c[2]), "+f"(c[3])
                 : "r"(a0), "r"(a1), "r"(a2), "r"(a3), "r"(b0), "r"(b1));
}

// ---- cp.async helpers ----
__device__ __forceinline__ void cp4(uint32_t dst, const void* src) {
    asm volatile("cp.async.ca.shared.global [%0], [%1], 4;" :: "r"(dst), "l"(src));
}
__device__ __forceinline__ void cp16(uint32_t dst, const void* src) {
    asm volatile("cp.async.cg.shared.global [%0], [%1], 16;" :: "r"(dst), "l"(src));
}
__device__ __forceinline__ void cp_commit() {
    asm volatile("cp.async.commit_group;");
}
__device__ __forceinline__ void cp_wait1() {
    asm volatile("cp.async.wait_group 1;");
}

// ef smem k-map within a row (stride 48): quads (k, k+4, k+8, k+12) contiguous
__device__ __host__ __forceinline__ int ef_off(int k) {
    return ((k >> 4) << 4) + ((k & 3) << 2) + (((k >> 3) & 1) << 1) + ((k >> 2) & 1);
}

// ---- kernel 1: node0 = node_fea @ Wn + bn ----
__global__ void __launch_bounds__(256) k_node_in(const float* __restrict__ nf,
                                                 const float* __restrict__ Wn,
                                                 const float* __restrict__ bn) {
    __shared__ float s_nf[8 * FN];
    int nbase = blockIdx.x * 8;
    for (int i = threadIdx.x; i < 8 * FN; i += 256)
        s_nf[i] = nf[(size_t)nbase * FN + i];
    __syncthreads();
    int g = threadIdx.x >> 5, c = threadIdx.x & 31;
    ull acc = pack2(bn[2 * c], bn[2 * c + 1]);
    const float* nr = &s_nf[g * FN];
#pragma unroll 4
    for (int k = 0; k < FN; k++) {
        ull w = *(const ull*)&Wn[k * Ff + 2 * c];
        fma2(acc, pack_dup(nr[k]), w);
    }
    *(ull*)&g_bufA[(size_t)(nbase + g) * Ff + 2 * c] = acc;
}

// ---- kernel 2: fold U into pre-arranged tf32 A fragments + dv ----
__global__ void __launch_bounds__(256) k_fold(const float* __restrict__ We,
                                              const float* __restrict__ be,
                                              const float* __restrict__ W1,
                                              const float* __restrict__ W2,
                                              const float* __restrict__ W3) {
    int l = blockIdx.x >> 3, gr = blockIdx.x & 7;
    const float* W = (l == 0) ? W1 : ((l == 1) ? W2 : W3);
    for (int i = threadIdx.x; i < 16 * 48; i += 256) {
        int r = i / 48, k = i - r * 48;
        int c = (r < 8) ? (gr * 8 + r) : (64 + gr * 8 + (r - 8));
        float u = 0.0f;
        if (k < FE) {
#pragma unroll 8
            for (int q = 0; q < Ff; q++)
                u = fmaf(We[k * Ff + q], W[(size_t)(128 + q) * Cc + c], u);
        }
        int kt = k >> 3, kin = k & 7;
        int q = ((r >= 8) ? 1 : 0) + ((kin >= 4) ? 2 : 0);
        int ln = (r & 7) * 4 + (kin & 3);
        g_Ua[(((l * 8 + gr) * 6 + kt) * 4 + q) * 32 + ln] = cvt_tf32(u);
    }
    if (threadIdx.x < 16) {
        int c = gr * 16 + threadIdx.x;
        float dv = 0.0f;
#pragma unroll 8
        for (int q = 0; q < Ff; q++)
            dv = fmaf(be[q], W[(size_t)(128 + q) * Cc + c], dv);
        g_dv[l * Cc + c] = dv;
    }
}

// ---- kernel 3: per-layer S/P precompute — 32 nodes/block, 8 nodes/thread ----
// Same pair-layout stores as R7; weight loads amortized over 2x the nodes.
__global__ void __launch_bounds__(256) k_SP(int srcSel, const float* __restrict__ W,
                                            const float* __restrict__ b, int l) {
    const float* node = srcSel ? g_bufB : g_bufA;
    __shared__ float s_nT[64 * 36];   // stride 36: aligned float4 reads, 4-way STS worst case
    int nbase = blockIdx.x * 32;
    for (int i = threadIdx.x; i < 2048; i += 256) {
        int k = i & 63, nl = i >> 6;
        int n = nbase + nl;
        s_nT[k * 36 + nl] = (n < Nn) ? node[(size_t)n * 64 + k] : 0.0f;
    }
    __syncthreads();
    int c = threadIdx.x & 63, gq = threadIdx.x >> 6;  // c: col pair, gq: 8-node group
    float2 bv = ((const float2*)b)[c];
    float2 dv = ((const float2*)(g_dv + l * Cc))[c];
    ull sInit = pack2(bv.x + dv.x, bv.y + dv.y);
    ull s[8], p[8];
#pragma unroll
    for (int t = 0; t < 8; t++) { s[t] = sInit; p[t] = 0ULL; }
#pragma unroll 4
    for (int k = 0; k < 64; k++) {
        ull wS = *(const ull*)&W[(size_t)k * Cc + 2 * c];
        ull wP = *(const ull*)&W[(size_t)(64 + k) * Cc + 2 * c];
        const float* nb = &s_nT[k * 36 + gq * 8];
        float4 n0 = *(const float4*)nb;
        float4 n1 = *(const float4*)(nb + 4);
        ull q0 = pack_dup(n0.x); fma2(s[0], q0, wS); fma2(p[0], q0, wP);
        ull q1 = pack_dup(n0.y); fma2(s[1], q1, wS); fma2(p[1], q1, wP);
        ull q2 = pack_dup(n0.z); fma2(s[2], q2, wS); fma2(p[2], q2, wP);
        ull q3 = pack_dup(n0.w); fma2(s[3], q3, wS); fma2(p[3], q3, wP);
        ull q4 = pack_dup(n1.x); fma2(s[4], q4, wS); fma2(p[4], q4, wP);
        ull q5 = pack_dup(n1.y); fma2(s[5], q5, wS); fma2(p[5], q5, wP);
        ull q6 = pack_dup(n1.z); fma2(s[6], q6, wS); fma2(p[6], q6, wP);
        ull q7 = pack_dup(n1.w); fma2(s[7], q7, wS); fma2(p[7], q7, wP);
    }
    int n0i = nbase + gq * 8;
    int base = (c < 32) ? (4 * c) : (4 * c - 127);
#pragma unroll
    for (int t = 0; t < 8; t++) {
        int n = n0i + t;
        if (n < Nn) {
            float x, y;
            unpack2(s[t], x, y);
            g_S[(size_t)n * Cc + base] = x;
            g_S[(size_t)n * Cc + base + 2] = y;
            unpack2(p[t], x, y);
            g_P[(size_t)n * Cc + base] = x;
            g_P[(size_t)n * Cc + base + 2] = y;
        }
    }
}

// ---- kernel 4: fused conv layer, 2-deep pipelined transposed tf32 mma (R7 EXACT) ----
__global__ void __launch_bounds__(256, 4) k_conv(int srcSel, int dstSel,
                                                 const float* __restrict__ ef,
                                                 const int* __restrict__ idx,
                                                 const float* __restrict__ alpha_p,
                                                 float* __restrict__ outp, int l) {
    const float* nodein = srcSel ? g_bufB : g_bufA;
    float* dst = (dstSel == 0) ? g_bufA : ((dstSel == 1) ? g_bufB : outp);

    __shared__ __align__(16) float s_ef[3][24 * 48];   // 13.5 KB triple-buffered ef tile
    __shared__ __align__(16) int s_idx[16 * 24];       // 1.5 KB all idx for block

    const int tid = threadIdx.x;
    const int w = tid >> 5, lane = tid & 31;
    const int lr = lane >> 2, lc = lane & 3;
    const int nbase = blockIdx.x * 16;

    // A fragments (24 coalesced loads, once per block)
    uint32_t Af[6][4];
    const uint32_t* Ua = g_Ua + (size_t)(l * 8 + w) * 6 * 128;
#pragma unroll
    for (int kt = 0; kt < 6; kt++)
#pragma unroll
        for (int q = 0; q < 4; q++)
            Af[kt][q] = Ua[kt * 128 + q * 32 + lane];

    // static zero pads: image of k=41..47 in every row, all 3 buffers
    for (int i = tid; i < 3 * 24 * 7; i += 256) {
        int bq = i / 168, r = i - bq * 168;
        int m = r / 7, k = 41 + (r - m * 7);
        s_ef[bq][m * 48 + ef_off(k)] = 0.0f;
    }

    // per-thread ef-prefetch dest offsets (node-invariant map)
    uint32_t eb[3];
    eb[0] = (uint32_t)__cvta_generic_to_shared(&s_ef[0][0]);
    eb[1] = (uint32_t)__cvta_generic_to_shared(&s_ef[1][0]);
    eb[2] = (uint32_t)__cvta_generic_to_shared(&s_ef[2][0]);
    uint32_t dq[4];
#pragma unroll
    for (int r = 0; r < 4; r++) {
        int t = tid + r * 256;
        int m = t / FE, k = t - m * FE;
        dq[r] = (uint32_t)(m * 48 + ef_off(k)) * 4;
    }
    const bool has3 = (tid < 24 * FE - 768);

    // prologue: idx staging + prefetch n0 (group 0); prefetch n1 (group 1)
    if (tid < 96)
        cp16((uint32_t)__cvta_generic_to_shared(s_idx) + tid * 16, idx + (size_t)nbase * 24 + tid * 4);
    {
        const float* src = ef + (size_t)nbase * 24 * FE;
        cp4(eb[0] + dq[0], src + tid);
        cp4(eb[0] + dq[1], src + tid + 256);
        cp4(eb[0] + dq[2], src + tid + 512);
        if (has3) cp4(eb[0] + dq[3], src + tid + 768);
        cp_commit();
        src += 24 * FE;
        cp4(eb[1] + dq[0], src + tid);
        cp4(eb[1] + dq[1], src + tid + 256);
        cp4(eb[1] + dq[2], src + tid + 512);
        if (has3) cp4(eb[1] + dq[3], src + tid + 768);
        cp_commit();
    }

    const float alpha = __ldg(alpha_p);
    const int jo = w * 8 + lr;  // orig feature index owned at lc==0
    int bi = 0, pf = 2;

    for (int ni = 0; ni < 16; ni++) {
        const int n = nbase + ni;

        cp_wait1();          // group for node ni complete; ni+1 may be in flight
        __syncthreads();     // also: all warps done with node ni-1's buffer

        // ---- prefetch node ni+2 into the buffer freed by ni-1 ----
        if (ni < 14) {
            uint32_t db = eb[pf];
            const float* src = ef + (size_t)(n + 2) * 24 * FE;
            cp4(db + dq[0], src + tid);
            cp4(db + dq[1], src + tid + 256);
            cp4(db + dq[2], src + tid + 512);
            if (has3) cp4(db + dq[3], src + tid + 768);
        }
        cp_commit();         // commit even when empty to keep group accounting uniform

        // ---- early loads: idx (int2 LDS) -> P float2 gathers + S + node-in ----
        int2 ii0 = *(const int2*)&s_idx[ni * 24 + 0 * 8 + 2 * lc];
        int2 ii1 = *(const int2*)&s_idx[ni * 24 + 1 * 8 + 2 * lc];
        int2 ii2 = *(const int2*)&s_idx[ni * 24 + 2 * 8 + 2 * lc];
        int iia[6] = {ii0.x, ii0.y, ii1.x, ii1.y, ii2.x, ii2.y};
        float2 Pv[6];
#pragma unroll
        for (int t = 0; t < 6; t++) {
            int iv = (iia[t] < 0) ? 0 : iia[t];
            Pv[t] = *(const float2*)&g_P[(size_t)iv * Cc + 2 * jo];
        }
        float2 Sv = *(const float2*)&g_S[(size_t)n * Cc + 2 * jo];
        float nin = __ldg(&nodein[(size_t)n * Ff + jo]);

        // ---- mma: 3 chains; B operands via LDS.128 (two k-steps per load) ----
        const float* se = s_ef[bi];
        const float* r0 = se + (0 * 8 + lr) * 48 + lc * 4;
        const float* r1 = se + (1 * 8 + lr) * 48 + lc * 4;
        const float* r2 = se + (2 * 8 + lr) * 48 + lc * 4;
        float c0[4] = {0, 0, 0, 0}, c1[4] = {0, 0, 0, 0}, c2[4] = {0, 0, 0, 0};
#pragma unroll
        for (int t = 0; t < 3; t++) {
            float4 q0 = *(const float4*)(r0 + t * 16);
            float4 q1 = *(const float4*)(r1 + t * 16);
            float4 q2 = *(const float4*)(r2 + t * 16);
            mma_tf32(c0, Af[2 * t][0], Af[2 * t][1], Af[2 * t][2], Af[2 * t][3],
                     __float_as_uint(q0.x), __float_as_uint(q0.y));
            mma_tf32(c1, Af[2 * t][0], Af[2 * t][1], Af[2 * t][2], Af[2 * t][3],
                     __float_as_uint(q1.x), __float_as_uint(q1.y));
            mma_tf32(c2, Af[2 * t][0], Af[2 * t][1], Af[2 * t][2], Af[2 * t][3],
                     __float_as_uint(q2.x), __float_as_uint(q2.y));
            mma_tf32(c0, Af[2 * t + 1][0], Af[2 * t + 1][1], Af[2 * t + 1][2], Af[2 * t + 1][3],
                     __float_as_uint(q0.z), __float_as_uint(q0.w));
            mma_tf32(c1, Af[2 * t + 1][0], Af[2 * t + 1][1], Af[2 * t + 1][2], Af[2 * t + 1][3],
                     __float_as_uint(q1.z), __float_as_uint(q1.w));
            mma_tf32(c2, Af[2 * t + 1][0], Af[2 * t + 1][1], Af[2 * t + 1][2], Af[2 * t + 1][3],
                     __float_as_uint(q2.z), __float_as_uint(q2.w));
        }

        // ---- epilogue: lane-local (filter, core) pairs ----
        float acc = 0.0f;
        if (iia[0] >= 0) acc += sigmoidf_(c0[0] + Sv.x + Pv[0].x) * softplusf_(c0[2] + Sv.y + Pv[0].y);
        if (iia[1] >= 0) acc += sigmoidf_(c0[1] + Sv.x + Pv[1].x) * softplusf_(c0[3] + Sv.y + Pv[1].y);
        if (iia[2] >= 0) acc += sigmoidf_(c1[0] + Sv.x + Pv[2].x) * softplusf_(c1[2] + Sv.y + Pv[2].y);
        if (iia[3] >= 0) acc += sigmoidf_(c1[1] + Sv.x + Pv[3].x) * softplusf_(c1[3] + Sv.y + Pv[3].y);
        if (iia[4] >= 0) acc += sigmoidf_(c2[0] + Sv.x + Pv[4].x) * softplusf_(c2[2] + Sv.y + Pv[4].y);
        if (iia[5] >= 0) acc += sigmoidf_(c2[1] + Sv.x + Pv[5].x) * softplusf_(c2[3] + Sv.y + Pv[5].y);

        acc += __shfl_xor_sync(0xffffffffu, acc, 1);
        acc += __shfl_xor_sync(0xffffffffu, acc, 2);

        if (lc == 0)
            dst[(size_t)n * Ff + jo] = softplusf_(fmaf(alpha, nin, acc));

        bi = (bi == 2) ? 0 : bi + 1;
        pf = (pf == 2) ? 0 : pf + 1;
    }
}

extern "C" void kernel_launch(void* const* d_in, const int* in_sizes, int n_in,
                              void* d_out, int out_size) {
    const float* nf  = (const float*)d_in[0];
    const float* ef  = (const float*)d_in[1];
    const int*   idx = (const int*)d_in[2];
    const float* Wn  = (const float*)d_in[3];
    const float* bn  = (const float*)d_in[4];
    const float* We  = (const float*)d_in[5];
    const float* be  = (const float*)d_in[6];
    const float* W[3] = {(const float*)d_in[7], (const float*)d_in[10], (const float*)d_in[13]};
    const float* b[3] = {(const float*)d_in[8], (const float*)d_in[11], (const float*)d_in[14]};
    const float* a[3] = {(const float*)d_in[9], (const float*)d_in[12], (const float*)d_in[15]};
    float* out = (float*)d_out;

    k_node_in<<<Nn / 8, 256>>>(nf, Wn, bn);              // -> g_bufA
    k_fold<<<24, 256>>>(We, be, W[0], W[1], W[2]);       // -> g_Ua, g_dv

    const int spGrid = (Nn + 31) / 32;                   // 1563
    // layer 1: A -> B
    k_SP<<<spGrid, 256>>>(0, W[0], b[0], 0);
    k_conv<<<Nn / 16, 256>>>(0, 1, ef, idx, a[0], out, 0);
    // layer 2: B -> A
    k_SP<<<spGrid, 256>>>(1, W[1], b[1], 1);
    k_conv<<<Nn / 16, 256>>>(1, 0, ef, idx, a[1], out, 1);
    // layer 3: A -> d_out
    k_SP<<<spGrid, 256>>>(0, W[2], b[2], 2);
    k_conv<<<Nn / 16, 256>>>(0, 2, ef, idx, a[2], out, 2);
}

// round 16
// speedup vs baseline: 1.7143x; 1.0786x over previous
#include <cuda_runtime.h>
#include <cstdint>

#define Nn 50000
#define Mm 24
#define FN 92
#define FE 41
#define Ff 64
#define Cc 128

typedef unsigned long long ull;

// ---- scratch (static device globals; no allocation) ----
__device__ float g_bufA[Nn * Ff];             // 12.8 MB
__device__ float g_bufB[Nn * Ff];             // 12.8 MB
__device__ float g_S[(size_t)Nn * Cc];        // 25.6 MB (quad layout: [(a*8+r)*4 + 2b + {0=f,1=c}], j=16a+8b+r)
__device__ float g_P[(size_t)Nn * Cc];        // 25.6 MB (quad layout)
__device__ uint32_t g_Ua[3 * 8 * 6 * 4 * 32]; // pre-fragmented tf32 A operands
__device__ float g_dv[3 * Cc];                // folded edge bias (orig col layout)

// ---- f32x2 packed helpers ----
__device__ __forceinline__ ull pack_dup(float x) {
    ull r; asm("mov.b64 %0, {%1, %1};" : "=l"(r) : "f"(x)); return r;
}
__device__ __forceinline__ ull pack2(float x, float y) {
    ull r; asm("mov.b64 %0, {%1, %2};" : "=l"(r) : "f"(x), "f"(y)); return r;
}
__device__ __forceinline__ void unpack2(ull v, float& x, float& y) {
    asm("mov.b64 {%0, %1}, %2;" : "=f"(x), "=f"(y) : "l"(v));
}
__device__ __forceinline__ void fma2(ull& acc, ull a, ull b) {
    asm("fma.rn.f32x2 %0, %1, %2, %0;" : "+l"(acc) : "l"(a), "l"(b));
}

// ---- fast activations (MUFU) ----
__device__ __forceinline__ float ex2_(float x) { float r; asm("ex2.approx.f32 %0, %1;" : "=f"(r) : "f"(x)); return r; }
__device__ __forceinline__ float lg2_(float x) { float r; asm("lg2.approx.f32 %0, %1;" : "=f"(r) : "f"(x)); return r; }
__device__ __forceinline__ float rcp_(float x) { float r; asm("rcp.approx.f32 %0, %1;" : "=f"(r) : "f"(x)); return r; }

__device__ __forceinline__ float sigmoidf_(float x) {
    return rcp_(1.0f + ex2_(-1.4426950408889634f * x));
}
__device__ __forceinline__ float softplusf_(float x) {
    float a = fabsf(x);
    float e = ex2_(-1.4426950408889634f * a);
    return fmaf(lg2_(1.0f + e), 0.6931471805599453f, fmaxf(x, 0.0f));
}

// ---- tf32 helpers ----
__device__ __forceinline__ uint32_t cvt_tf32(float x) {
    uint32_t r; asm("cvt.rna.tf32.f32 %0, %1;" : "=r"(r) : "f"(x)); return r;
}
__device__ __forceinline__ void mma_tf32(float* c,
                                         uint32_t a0, uint32_t a1, uint32_t a2, uint32_t a3,
                                         uint32_t b0, uint32_t b1) {
    asm volatile("mma.sync.aligned.m16n8k8.row.col.f32.tf32.tf32.f32 "
                 "{%0,%1,%2,%3}, {%4,%5,%6,%7}, {%8,%9}, {%0,%1,%2,%3};"
                 : "+f"(c[0]), "+f"(c[1]), "+f"(c[2]), "+f"(c[3])
                 : "r"(a0), "r"(a1), "r"(a2), "r"(a3), "r"(b0), "r"(b1));
}

// ---- cp.async helpers ----
__device__ __forceinline__ void cp4(uint32_t dst, const void* src) {
    asm volatile("cp.async.ca.shared.global [%0], [%1], 4;" :: "r"(dst), "l"(src));
}
__device__ __forceinline__ void cp16(uint32_t dst, const void* src) {
    asm volatile("cp.async.cg.shared.global [%0], [%1], 16;" :: "r"(dst), "l"(src));
}
__device__ __forceinline__ void cp_commit() {
    asm volatile("cp.async.commit_group;");
}
__device__ __forceinline__ void cp_wait1() {
    asm volatile("cp.async.wait_group 1;");
}

// ef smem k-map within a row (stride 48): quads (k, k+4, k+8, k+12) contiguous
__device__ __host__ __forceinline__ int ef_off(int k) {
    return ((k >> 4) << 4) + ((k & 3) << 2) + (((k >> 3) & 1) << 1) + ((k >> 2) & 1);
}

// ---- kernel 1: node0 = node_fea @ Wn + bn ----
__global__ void __launch_bounds__(256) k_node_in(const float* __restrict__ nf,
                                                 const float* __restrict__ Wn,
                                                 const float* __restrict__ bn) {
    __shared__ float s_nf[8 * FN];
    int nbase = blockIdx.x * 8;
    for (int i = threadIdx.x; i < 8 * FN; i += 256)
        s_nf[i] = nf[(size_t)nbase * FN + i];
    __syncthreads();
    int g = threadIdx.x >> 5, c = threadIdx.x & 31;
    ull acc = pack2(bn[2 * c], bn[2 * c + 1]);
    const float* nr = &s_nf[g * FN];
#pragma unroll 4
    for (int k = 0; k < FN; k++) {
        ull w = *(const ull*)&Wn[k * Ff + 2 * c];
        fma2(acc, pack_dup(nr[k]), w);
    }
    *(ull*)&g_bufA[(size_t)(nbase + g) * Ff + 2 * c] = acc;
}

// ---- kernel 2: fold U into pre-arranged tf32 A fragments + dv ----
__global__ void __launch_bounds__(256) k_fold(const float* __restrict__ We,
                                              const float* __restrict__ be,
                                              const float* __restrict__ W1,
                                              const float* __restrict__ W2,
                                              const float* __restrict__ W3) {
    int l = blockIdx.x >> 3, gr = blockIdx.x & 7;
    const float* W = (l == 0) ? W1 : ((l == 1) ? W2 : W3);
    for (int i = threadIdx.x; i < 16 * 48; i += 256) {
        int r = i / 48, k = i - r * 48;
        int c = (r < 8) ? (gr * 8 + r) : (64 + gr * 8 + (r - 8));
        float u = 0.0f;
        if (k < FE) {
#pragma unroll 8
            for (int q = 0; q < Ff; q++)
                u = fmaf(We[k * Ff + q], W[(size_t)(128 + q) * Cc + c], u);
        }
        int kt = k >> 3, kin = k & 7;
        int q = ((r >= 8) ? 1 : 0) + ((kin >= 4) ? 2 : 0);
        int ln = (r & 7) * 4 + (kin & 3);
        g_Ua[(((l * 8 + gr) * 6 + kt) * 4 + q) * 32 + ln] = cvt_tf32(u);
    }
    if (threadIdx.x < 16) {
        int c = gr * 16 + threadIdx.x;
        float dv = 0.0f;
#pragma unroll 8
        for (int q = 0; q < Ff; q++)
            dv = fmaf(be[q], W[(size_t)(128 + q) * Cc + c], dv);
        g_dv[l * Cc + c] = dv;
    }
}

// ---- kernel 3: per-layer S/P precompute — 32 nodes/block, 8 nodes/thread ----
// quad store layout: j=16a+8b+r -> filter at (a*8+r)*4 + 2b, core at +1
__global__ void __launch_bounds__(256) k_SP(int srcSel, const float* __restrict__ W,
                                            const float* __restrict__ b, int l) {
    const float* node = srcSel ? g_bufB : g_bufA;
    __shared__ float s_nT[64 * 36];
    int nbase = blockIdx.x * 32;
    for (int i = threadIdx.x; i < 2048; i += 256) {
        int k = i & 63, nl = i >> 6;
        int n = nbase + nl;
        s_nT[k * 36 + nl] = (n < Nn) ? node[(size_t)n * 64 + k] : 0.0f;
    }
    __syncthreads();
    int c = threadIdx.x & 63, gq = threadIdx.x >> 6;
    float2 bv = ((const float2*)b)[c];
    float2 dv = ((const float2*)(g_dv + l * Cc))[c];
    ull sInit = pack2(bv.x + dv.x, bv.y + dv.y);
    ull s[8], p[8];
#pragma unroll
    for (int t = 0; t < 8; t++) { s[t] = sInit; p[t] = 0ULL; }
#pragma unroll 4
    for (int k = 0; k < 64; k++) {
        ull wS = *(const ull*)&W[(size_t)k * Cc + 2 * c];
        ull wP = *(const ull*)&W[(size_t)(64 + k) * Cc + 2 * c];
        const float* nb = &s_nT[k * 36 + gq * 8];
        float4 n0 = *(const float4*)nb;
        float4 n1 = *(const float4*)(nb + 4);
        ull q0 = pack_dup(n0.x); fma2(s[0], q0, wS); fma2(p[0], q0, wP);
        ull q1 = pack_dup(n0.y); fma2(s[1], q1, wS); fma2(p[1], q1, wP);
        ull q2 = pack_dup(n0.z); fma2(s[2], q2, wS); fma2(p[2], q2, wP);
        ull q3 = pack_dup(n0.w); fma2(s[3], q3, wS); fma2(p[3], q3, wP);
        ull q4 = pack_dup(n1.x); fma2(s[4], q4, wS); fma2(p[4], q4, wP);
        ull q5 = pack_dup(n1.y); fma2(s[5], q5, wS); fma2(p[5], q5, wP);
        ull q6 = pack_dup(n1.z); fma2(s[6], q6, wS); fma2(p[6], q6, wP);
        ull q7 = pack_dup(n1.w); fma2(s[7], q7, wS); fma2(p[7], q7, wP);
    }
    int n0i = nbase + gq * 8;
    // orig gated col pair (2c, 2c+1): j = 2c & 63, core if c >= 32
    int j = (2 * c) & 63;
    int sl = ((j >> 4) * 8 + (j & 7)) * 4 + 2 * ((j >> 3) & 1) + ((c >= 32) ? 1 : 0);
#pragma unroll
    for (int t = 0; t < 8; t++) {
        int n = n0i + t;
        if (n < Nn) {
            float x, y;
            unpack2(s[t], x, y);
            g_S[(size_t)n * Cc + sl] = x;
            g_S[(size_t)n * Cc + sl + 4] = y;
            unpack2(p[t], x, y);
            g_P[(size_t)n * Cc + sl] = x;
            g_P[(size_t)n * Cc + sl + 4] = y;
        }
    }
}

// ---- kernel 4: fused conv layer — M32/warp, 4 warps, 8 nodes/block ----
__global__ void __launch_bounds__(128, 4) k_conv(int srcSel, int dstSel,
                                                 const float* __restrict__ ef,
                                                 const int* __restrict__ idx,
                                                 const float* __restrict__ alpha_p,
                                                 float* __restrict__ outp, int l) {
    const float* nodein = srcSel ? g_bufB : g_bufA;
    float* dst = (dstSel == 0) ? g_bufA : ((dstSel == 1) ? g_bufB : outp);

    __shared__ __align__(16) float s_ef[3][24 * 48];   // 13.5 KB triple-buffered ef tile
    __shared__ __align__(16) int s_idx[8 * 24];        // 768 B

    const int tid = threadIdx.x;
    const int w = tid >> 5, lane = tid & 31;
    const int lr = lane >> 2, lc = lane & 3;
    const int nbase = blockIdx.x * 8;

    // A fragments: TWO panels per warp (feature groups 2w, 2w+1)
    uint32_t Af[6][4], Ag[6][4];
    const uint32_t* Ua0 = g_Ua + (size_t)(l * 8 + 2 * w) * 768;
#pragma unroll
    for (int kt = 0; kt < 6; kt++)
#pragma unroll
        for (int q = 0; q < 4; q++) {
            Af[kt][q] = Ua0[kt * 128 + q * 32 + lane];
            Ag[kt][q] = Ua0[768 + kt * 128 + q * 32 + lane];
        }

    // static zero pads: image of k=41..47 in every row, all 3 buffers
    for (int i = tid; i < 3 * 24 * 7; i += 128) {
        int bq = i / 168, r = i - bq * 168;
        int m = r / 7, k = 41 + (r - m * 7);
        s_ef[bq][m * 48 + ef_off(k)] = 0.0f;
    }

    // per-thread ef-prefetch dest offsets (node-invariant map); 8 slots/thread
    uint32_t eb[3];
    eb[0] = (uint32_t)__cvta_generic_to_shared(&s_ef[0][0]);
    eb[1] = (uint32_t)__cvta_generic_to_shared(&s_ef[1][0]);
    eb[2] = (uint32_t)__cvta_generic_to_shared(&s_ef[2][0]);
    uint32_t dq[8];
#pragma unroll
    for (int r = 0; r < 8; r++) {
        int t = tid + r * 128;
        int m = t / FE, k = t - m * FE;
        dq[r] = (uint32_t)(m * 48 + ef_off(k)) * 4;
    }
    const bool has7 = (tid < 24 * FE - 896);   // tid < 88

    // prologue: idx staging + prefetch n0 (group 0); n1 (group 1)
    if (tid < 48)
        cp16((uint32_t)__cvta_generic_to_shared(s_idx) + tid * 16, idx + (size_t)nbase * 24 + tid * 4);
    {
        const float* src = ef + (size_t)nbase * 24 * FE;
#pragma unroll
        for (int r = 0; r < 7; r++) cp4(eb[0] + dq[r], src + tid + r * 128);
        if (has7) cp4(eb[0] + dq[7], src + tid + 896);
        cp_commit();
        src += 24 * FE;
#pragma unroll
        for (int r = 0; r < 7; r++) cp4(eb[1] + dq[r], src + tid + r * 128);
        if (has7) cp4(eb[1] + dq[7], src + tid + 896);
        cp_commit();
    }

    const float alpha = __ldg(alpha_p);
    const int j0 = 16 * w + lr, j1 = j0 + 8;
    const int pos4 = (w * 8 + lr) * 4;   // float4 slot in quad S/P layout
    int bi = 0, pf = 2;

    for (int ni = 0; ni < 8; ni++) {
        const int n = nbase + ni;

        cp_wait1();          // group for node ni complete; ni+1 may be in flight
        __syncthreads();     // all warps done with node ni-1's buffer

        // ---- prefetch node ni+2 into the freed buffer ----
        if (ni < 6) {
            uint32_t db = eb[pf];
            const float* src = ef + (size_t)(n + 2) * 24 * FE;
#pragma unroll
            for (int r = 0; r < 7; r++) cp4(db + dq[r], src + tid + r * 128);
            if (has7) cp4(db + dq[7], src + tid + 896);
        }
        cp_commit();         // uniform group accounting

        // ---- early loads ----
        int2 ii0 = *(const int2*)&s_idx[ni * 24 + 0 * 8 + 2 * lc];
        int2 ii1 = *(const int2*)&s_idx[ni * 24 + 1 * 8 + 2 * lc];
        int2 ii2 = *(const int2*)&s_idx[ni * 24 + 2 * 8 + 2 * lc];
        int iia[6] = {ii0.x, ii0.y, ii1.x, ii1.y, ii2.x, ii2.y};
        float4 Sv = *(const float4*)&g_S[(size_t)n * Cc + pos4];
        float nin0 = __ldg(&nodein[(size_t)n * Ff + j0]);
        float nin1 = __ldg(&nodein[(size_t)n * Ff + j1]);
        float4 Pv[6];
#pragma unroll
        for (int t = 0; t < 6; t++) {
            int iv = (iia[t] < 0) ? 0 : iia[t];
            Pv[t] = *(const float4*)&g_P[(size_t)iv * Cc + pos4];
        }

        // ---- mma: one B load set feeds both panels (36 mma) ----
        const float* se = s_ef[bi];
        const float* r0 = se + (0 * 8 + lr) * 48 + lc * 4;
        const float* r1 = se + (1 * 8 + lr) * 48 + lc * 4;
        const float* r2 = se + (2 * 8 + lr) * 48 + lc * 4;
        float c0[4] = {0, 0, 0, 0}, c1[4] = {0, 0, 0, 0}, c2[4] = {0, 0, 0, 0};
        float d0[4] = {0, 0, 0, 0}, d1[4] = {0, 0, 0, 0}, d2[4] = {0, 0, 0, 0};
#pragma unroll
        for (int t = 0; t < 3; t++) {
            float4 q0 = *(const float4*)(r0 + t * 16);
            float4 q1 = *(const float4*)(r1 + t * 16);
            float4 q2 = *(const float4*)(r2 + t * 16);
            uint32_t b0x = __float_as_uint(q0.x), b0y = __float_as_uint(q0.y);
            uint32_t b1x = __float_as_uint(q1.x), b1y = __float_as_uint(q1.y);
            uint32_t b2x = __float_as_uint(q2.x), b2y = __float_as_uint(q2.y);
            mma_tf32(c0, Af[2 * t][0], Af[2 * t][1], Af[2 * t][2], Af[2 * t][3], b0x, b0y);
            mma_tf32(d0, Ag[2 * t][0], Ag[2 * t][1], Ag[2 * t][2], Ag[2 * t][3], b0x, b0y);
            mma_tf32(c1, Af[2 * t][0], Af[2 * t][1], Af[2 * t][2], Af[2 * t][3], b1x, b1y);
            mma_tf32(d1, Ag[2 * t][0], Ag[2 * t][1], Ag[2 * t][2], Ag[2 * t][3], b1x, b1y);
            mma_tf32(c2, Af[2 * t][0], Af[2 * t][1], Af[2 * t][2], Af[2 * t][3], b2x, b2y);
            mma_tf32(d2, Ag[2 * t][0], Ag[2 * t][1], Ag[2 * t][2], Ag[2 * t][3], b2x, b2y);
            uint32_t b0z = __float_as_uint(q0.z), b0w = __float_as_uint(q0.w);
            uint32_t b1z = __float_as_uint(q1.z), b1w = __float_as_uint(q1.w);
            uint32_t b2z = __float_as_uint(q2.z), b2w = __float_as_uint(q2.w);
            mma_tf32(c0, Af[2 * t + 1][0], Af[2 * t + 1][1], Af[2 * t + 1][2], Af[2 * t + 1][3], b0z, b0w);
            mma_tf32(d0, Ag[2 * t + 1][0], Ag[2 * t + 1][1], Ag[2 * t + 1][2], Ag[2 * t + 1][3], b0z, b0w);
            mma_tf32(c1, Af[2 * t + 1][0], Af[2 * t + 1][1], Af[2 * t + 1][2], Af[2 * t + 1][3], b1z, b1w);
            mma_tf32(d1, Ag[2 * t + 1][0], Ag[2 * t + 1][1], Ag[2 * t + 1][2], Ag[2 * t + 1][3], b1z, b1w);
            mma_tf32(c2, Af[2 * t + 1][0], Af[2 * t + 1][1], Af[2 * t + 1][2], Af[2 * t + 1][3], b2z, b2w);
            mma_tf32(d2, Ag[2 * t + 1][0], Ag[2 * t + 1][1], Ag[2 * t + 1][2], Ag[2 * t + 1][3], b2z, b2w);
        }

        // ---- epilogue: both feature groups, lane-local pairs ----
        float acc0 = 0.0f, acc1 = 0.0f;
        if (iia[0] >= 0) {
            acc0 += sigmoidf_(c0[0] + Sv.x + Pv[0].x) * softplusf_(c0[2] + Sv.y + Pv[0].y);
            acc1 += sigmoidf_(d0[0] + Sv.z + Pv[0].z) * softplusf_(d0[2] + Sv.w + Pv[0].w);
        }
        if (iia[1] >= 0) {
            acc0 += sigmoidf_(c0[1] + Sv.x + Pv[1].x) * softplusf_(c0[3] + Sv.y + Pv[1].y);
            acc1 += sigmoidf_(d0[1] + Sv.z + Pv[1].z) * softplusf_(d0[3] + Sv.w + Pv[1].w);
        }
        if (iia[2] >= 0) {
            acc0 += sigmoidf_(c1[0] + Sv.x + Pv[2].x) * softplusf_(c1[2] + Sv.y + Pv[2].y);
            acc1 += sigmoidf_(d1[0] + Sv.z + Pv[2].z) * softplusf_(d1[2] + Sv.w + Pv[2].w);
        }
        if (iia[3] >= 0) {
            acc0 += sigmoidf_(c1[1] + Sv.x + Pv[3].x) * softplusf_(c1[3] + Sv.y + Pv[3].y);
            acc1 += sigmoidf_(d1[1] + Sv.z + Pv[3].z) * softplusf_(d1[3] + Sv.w + Pv[3].w);
        }
        if (iia[4] >= 0) {
            acc0 += sigmoidf_(c2[0] + Sv.x + Pv[4].x) * softplusf_(c2[2] + Sv.y + Pv[4].y);
            acc1 += sigmoidf_(d2[0] + Sv.z + Pv[4].z) * softplusf_(d2[2] + Sv.w + Pv[4].w);
        }
        if (iia[5] >= 0) {
            acc0 += sigmoidf_(c2[1] + Sv.x + Pv[5].x) * softplusf_(c2[3] + Sv.y + Pv[5].y);
            acc1 += sigmoidf_(d2[1] + Sv.z + Pv[5].z) * softplusf_(d2[3] + Sv.w + Pv[5].w);
        }

        acc0 += __shfl_xor_sync(0xffffffffu, acc0, 1);
        acc0 += __shfl_xor_sync(0xffffffffu, acc0, 2);
        acc1 += __shfl_xor_sync(0xffffffffu, acc1, 1);
        acc1 += __shfl_xor_sync(0xffffffffu, acc1, 2);

        if (lc == 0) {
            dst[(size_t)n * Ff + j0] = softplusf_(fmaf(alpha, nin0, acc0));
            dst[(size_t)n * Ff + j1] = softplusf_(fmaf(alpha, nin1, acc1));
        }

        bi = (bi == 2) ? 0 : bi + 1;
        pf = (pf == 2) ? 0 : pf + 1;
    }
}

extern "C" void kernel_launch(void* const* d_in, const int* in_sizes, int n_in,
                              void* d_out, int out_size) {
    const float* nf  = (const float*)d_in[0];
    const float* ef  = (const float*)d_in[1];
    const int*   idx = (const int*)d_in[2];
    const float* Wn  = (const float*)d_in[3];
    const float* bn  = (const float*)d_in[4];
    const float* We  = (const float*)d_in[5];
    const float* be  = (const float*)d_in[6];
    const float* W[3] = {(const float*)d_in[7], (const float*)d_in[10], (const float*)d_in[13]};
    const float* b[3] = {(const float*)d_in[8], (const float*)d_in[11], (const float*)d_in[14]};
    const float* a[3] = {(const float*)d_in[9], (const float*)d_in[12], (const float*)d_in[15]};
    float* out = (float*)d_out;

    k_node_in<<<Nn / 8, 256>>>(nf, Wn, bn);              // -> g_bufA
    k_fold<<<24, 256>>>(We, be, W[0], W[1], W[2]);       // -> g_Ua, g_dv

    const int spGrid = (Nn + 31) / 32;                   // 1563
    const int cvGrid = Nn / 8;                           // 6250
    // layer 1: A -> B
    k_SP<<<spGrid, 256>>>(0, W[0], b[0], 0);
    k_conv<<<cvGrid, 128>>>(0, 1, ef, idx, a[0], out, 0);
    // layer 2: B -> A
    k_SP<<<spGrid, 256>>>(1, W[1], b[1], 1);
    k_conv<<<cvGrid, 128>>>(1, 0, ef, idx, a[1], out, 1);
    // layer 3: A -> d_out
    k_SP<<<spGrid, 256>>>(0, W[2], b[2], 2);
    k_conv<<<cvGrid, 128>>>(0, 2, ef, idx, a[2], out, 2);
}